// round 2
// baseline (speedup 1.0000x reference)
#include <cuda_runtime.h>
#include <math.h>

#define BB   64
#define TT   512
#define EE   256
#define HH   512
#define GG   2048   // 4*H
#define NTAG 12
#define NCLS 10
#define PADT 0
#define BOST 10
#define EOST 11

// ---------------- scratch (device globals; allocation-free) ----------------
__device__ __align__(16) float g_xproj[(size_t)2 * TT * BB * GG]; // [dir][t][b][g], NO bias
__device__ __align__(16) float g_h[2][2][BB][HH];                  // [phase][dir][b][k]
__device__ __align__(16) float g_c[2][BB][HH];                     // [dir][b][k]
__device__ __align__(16) float g_hout[2][BB][TT][HH];              // masked outputs m*h_new
__device__ __align__(16) float g_emis[BB][TT][NTAG];

// ---------------- XLA-matching elementwise math ----------------
// XLA f32 tanh: |x| < 0.0004 -> x; clamp to +-7.90531110689510; rational P(x^2)/Q(x^2)
__device__ __forceinline__ float xla_tanh(float x) {
    if (fabsf(x) < 0.0004f) return x;
    float xc = fminf(fmaxf(x, -7.90531110689510f), 7.90531110689510f);
    float x2 = __fmul_rn(xc, xc);
    float p = -2.76076847742355e-16f;
    p = fmaf(p, x2, 2.00018790482477e-13f);
    p = fmaf(p, x2, -8.60467152213735e-11f);
    p = fmaf(p, x2, 5.12229709037114e-08f);
    p = fmaf(p, x2, 1.48572235717979e-05f);
    p = fmaf(p, x2, 6.37261928875436e-04f);
    p = fmaf(p, x2, 4.89352455891786e-03f);
    p = __fmul_rn(xc, p);
    float q = 1.19825839466702e-06f;
    q = fmaf(q, x2, 1.18534705686654e-04f);
    q = fmaf(q, x2, 2.26843463243900e-03f);
    q = fmaf(q, x2, 4.89352518554385e-03f);
    return __fdiv_rn(p, q);
}

// XLA logistic expansion: 1 / (1 + exp(-x))
__device__ __forceinline__ float xla_sigmoid(float x) {
    return __fdiv_rn(1.0f, __fadd_rn(1.0f, expf(-x)));
}

// ---------------- init: zero h(phase0) and c ----------------
__global__ void k_init() {
    int i = blockIdx.x * blockDim.x + threadIdx.x;
    if (i < 2 * BB * HH) {
        ((float*)g_h)[i] = 0.0f;   // phase 0, both dirs
        ((float*)g_c)[i] = 0.0f;
    }
}

// ---------------- input projection GEMM (no bias) ----------------
// out[dir][t][b][g] = sum_k emb[x[b,t]][k] * W_ih[dir][g][k]
__global__ __launch_bounds__(256) void k_proj(const int* __restrict__ x,
                                              const float* __restrict__ emb,
                                              const float* __restrict__ wf,
                                              const float* __restrict__ wb) {
    const int dir = blockIdx.z;
    const float* __restrict__ W = dir ? wb : wf;
    const int m0 = blockIdx.x * 128;
    const int n0 = blockIdx.y * 128;

    __shared__ int toks[128];
    __shared__ __align__(16) float As[16 * 132];
    __shared__ __align__(16) float Bs[16 * 132];

    const int tid = threadIdx.x;
    if (tid < 128) toks[tid] = x[m0 + tid];
    __syncthreads();

    const int ty = tid >> 4;   // 0..15 -> rows ty*8
    const int tx = tid & 15;   // 0..15 -> cols tx*8

    const float* arow[8];
    const float* brow[8];
#pragma unroll
    for (int i = 0; i < 8; i++) {
        int lin = i * 256 + tid;
        int mi  = lin >> 4;
        arow[i] = emb + (size_t)toks[mi] * EE;
        brow[i] = W + (size_t)(n0 + mi) * EE;
    }

    float acc[8][8];
#pragma unroll
    for (int i = 0; i < 8; i++)
#pragma unroll
        for (int j = 0; j < 8; j++) acc[i][j] = 0.0f;

    for (int k0 = 0; k0 < EE; k0 += 16) {
#pragma unroll
        for (int i = 0; i < 8; i++) {
            int lin = i * 256 + tid;
            int ki = lin & 15, mi = lin >> 4;
            As[ki * 132 + mi] = arow[i][k0 + ki];
            Bs[ki * 132 + mi] = brow[i][k0 + ki];
        }
        __syncthreads();
#pragma unroll
        for (int k = 0; k < 16; k++) {
            float4 a0 = *(const float4*)&As[k * 132 + ty * 8];
            float4 a1 = *(const float4*)&As[k * 132 + ty * 8 + 4];
            float4 b0 = *(const float4*)&Bs[k * 132 + tx * 8];
            float4 b1 = *(const float4*)&Bs[k * 132 + tx * 8 + 4];
            float av[8] = {a0.x, a0.y, a0.z, a0.w, a1.x, a1.y, a1.z, a1.w};
            float bv[8] = {b0.x, b0.y, b0.z, b0.w, b1.x, b1.y, b1.z, b1.w};
#pragma unroll
            for (int i = 0; i < 8; i++)
#pragma unroll
                for (int j = 0; j < 8; j++) acc[i][j] = fmaf(av[i], bv[j], acc[i][j]);
        }
        __syncthreads();
    }

#pragma unroll
    for (int i = 0; i < 8; i++) {
        int m = m0 + ty * 8 + i;
        int b = m >> 9;        // /T
        int t = m & (TT - 1);
        size_t base = ((size_t)(dir * TT + t) * BB + b) * GG + n0 + tx * 8;
        float4 v0 = make_float4(acc[i][0], acc[i][1], acc[i][2], acc[i][3]);
        float4 v1 = make_float4(acc[i][4], acc[i][5], acc[i][6], acc[i][7]);
        *(float4*)&g_xproj[base]     = v0;
        *(float4*)&g_xproj[base + 4] = v1;
    }
}

// ---------------- fused LSTM step (both directions) ----------------
__global__ __launch_bounds__(128) void k_step(const int* __restrict__ x,
                                              const float* __restrict__ whf,
                                              const float* __restrict__ whb,
                                              const float* __restrict__ bfp,
                                              const float* __restrict__ bbp,
                                              int s) {
    const int dir = blockIdx.y;
    const int t   = dir ? (TT - 1 - s) : s;
    const int p   = s & 1;
    const float* __restrict__ W    = dir ? whb : whf;
    const float* __restrict__ bias = dir ? bbp : bfp;
    const int hh0 = blockIdx.x * 8;

    __shared__ __align__(16) float As[16 * 68];  // h_prev tile [k][b]
    __shared__ __align__(16) float Bs[16 * 36];  // W tile      [k][c]
    __shared__ __align__(16) float sg[64 * 36];  // gates       [b][c]

    const int tid = threadIdx.x;
    const int ty = tid >> 3;  // 0..15 -> rows ty*4
    const int tx = tid & 7;   // 0..7  -> cols tx*4

    const float* __restrict__ hprev = &g_h[p][dir][0][0];

    float acc[4][4];
#pragma unroll
    for (int i = 0; i < 4; i++)
#pragma unroll
        for (int j = 0; j < 4; j++) acc[i][j] = 0.0f;

    for (int k0 = 0; k0 < HH; k0 += 16) {
#pragma unroll
        for (int i = 0; i < 8; i++) {          // 1024 elems / 128 thr
            int lin = i * 128 + tid;
            int ki = lin & 15, bi = lin >> 4;
            As[ki * 68 + bi] = hprev[bi * HH + k0 + ki];
        }
#pragma unroll
        for (int i = 0; i < 4; i++) {          // 512 elems / 128 thr
            int lin = i * 128 + tid;
            int ki = lin & 15, ci = lin >> 4;
            int q = ci >> 3, hl = ci & 7;
            Bs[ki * 36 + ci] = W[(size_t)(q * HH + hh0 + hl) * HH + k0 + ki];
        }
        __syncthreads();
#pragma unroll
        for (int k = 0; k < 16; k++) {
            float4 a = *(const float4*)&As[k * 68 + ty * 4];
            float4 bv = *(const float4*)&Bs[k * 36 + tx * 4];
            float av[4] = {a.x, a.y, a.z, a.w};
            float bw[4] = {bv.x, bv.y, bv.z, bv.w};
#pragma unroll
            for (int i = 0; i < 4; i++)
#pragma unroll
                for (int j = 0; j < 4; j++) acc[i][j] = fmaf(av[i], bw[j], acc[i][j]);
        }
        __syncthreads();
    }

    // gates = (xw + hw) + b  (exact XLA add order), deposit into smem
#pragma unroll
    for (int i = 0; i < 4; i++) {
        int b = ty * 4 + i;
        int ci = tx * 4;
        int q = ci >> 3, hl = ci & 7;
        int gc = q * HH + hh0 + hl;
        float4 xp = *(const float4*)&g_xproj[((size_t)(dir * TT + t) * BB + b) * GG + gc];
        float4 bi4 = *(const float4*)&bias[gc];
        sg[b * 36 + ci + 0] = __fadd_rn(__fadd_rn(xp.x, acc[i][0]), bi4.x);
        sg[b * 36 + ci + 1] = __fadd_rn(__fadd_rn(xp.y, acc[i][1]), bi4.y);
        sg[b * 36 + ci + 2] = __fadd_rn(__fadd_rn(xp.z, acc[i][2]), bi4.z);
        sg[b * 36 + ci + 3] = __fadd_rn(__fadd_rn(xp.w, acc[i][3]), bi4.w);
    }
    __syncthreads();

    // fused LSTM cell: 512 (b, hl) items, 4 per thread — XLA-exact elementwise
#pragma unroll
    for (int e = 0; e < 4; e++) {
        int item = e * 128 + tid;
        int b = item >> 3, hl = item & 7;
        int hh = hh0 + hl;
        float iv = sg[b * 36 + 0  + hl];
        float fv = sg[b * 36 + 8  + hl];
        float gv = sg[b * 36 + 16 + hl];
        float ov = sg[b * 36 + 24 + hl];
        float co = g_c[dir][b][hh];
        float ho = hprev[b * HH + hh];
        float si = xla_sigmoid(iv);
        float sf = xla_sigmoid(fv);
        float so = xla_sigmoid(ov);
        float tg = xla_tanh(gv);
        float cn = __fadd_rn(__fmul_rn(sf, co), __fmul_rn(si, tg));
        float hc = __fmul_rn(so, xla_tanh(cn));
        bool  mm = (x[b * TT + t] != PADT);
        g_c[dir][b][hh]        = mm ? cn : co;
        g_h[p ^ 1][dir][b][hh] = mm ? hc : ho;
        g_hout[dir][b][t][hh]  = mm ? hc : 0.0f;
    }
}

// ---------------- emissions: warp per (b,t), 12 outputs, K=1024 ----------------
__global__ __launch_bounds__(256) void k_emis(const float* __restrict__ fcw,
                                              const float* __restrict__ fcb) {
    int w = blockIdx.x * 8 + (threadIdx.x >> 5);
    int lane = threadIdx.x & 31;
    int b = w >> 9;
    int t = w & (TT - 1);
    const float* __restrict__ hf = &g_hout[0][b][t][0];
    const float* __restrict__ hb = &g_hout[1][b][t][0];
    float acc[NTAG];
#pragma unroll
    for (int j = 0; j < NTAG; j++) acc[j] = 0.0f;
    for (int it = 0; it < 32; it++) {
        int k = it * 32 + lane;
        float hv = (k < HH) ? hf[k] : hb[k - HH];
#pragma unroll
        for (int j = 0; j < NTAG; j++) acc[j] = fmaf(hv, fcw[j * (2 * HH) + k], acc[j]);
    }
#pragma unroll
    for (int j = 0; j < NTAG; j++)
#pragma unroll
        for (int o = 16; o > 0; o >>= 1) acc[j] += __shfl_xor_sync(0xffffffffu, acc[j], o);
    if (lane == 0) {
#pragma unroll
        for (int j = 0; j < NTAG; j++) g_emis[b][t][j] = __fadd_rn(acc[j], fcb[j]);
    }
}

// ---------------- class probabilities: warp per batch ----------------
__global__ void k_cls(const float* __restrict__ fc2w, const float* __restrict__ fc2b,
                      float* __restrict__ out) {
    int b = blockIdx.x;
    int lane = threadIdx.x;
    const float* __restrict__ hf = &g_h[0][0][b][0];  // final phase = 0
    const float* __restrict__ hb = &g_h[0][1][b][0];
    float logit[NCLS];
#pragma unroll
    for (int j = 0; j < NCLS; j++) {
        float p = 0.0f;
        for (int it = 0; it < 32; it++) {
            int k = it * 32 + lane;
            float hv = (k < HH) ? hf[k] : hb[k - HH];
            p = fmaf(hv, fc2w[j * (2 * HH) + k], p);
        }
#pragma unroll
        for (int o = 16; o > 0; o >>= 1) p += __shfl_xor_sync(0xffffffffu, p, o);
        logit[j] = __fadd_rn(p, fc2b[j]);
    }
    float mx = logit[0];
#pragma unroll
    for (int j = 1; j < NCLS; j++) mx = fmaxf(mx, logit[j]);
    float ex[NCLS];
    float sum = 0.0f;
#pragma unroll
    for (int j = 0; j < NCLS; j++) {
        ex[j] = expf(__fadd_rn(logit[j], -mx));
        sum = __fadd_rn(sum, ex[j]);
    }
    if (lane == 0) {
        float* o = out + BB + BB * TT + b * NCLS;
#pragma unroll
        for (int j = 0; j < NCLS; j++) o[j] = __fdiv_rn(ex[j], sum);
    }
}

// ---------------- Viterbi: warp per batch, backpointers in SMEM ----------------
__global__ void k_vit(const int* __restrict__ x, const float* __restrict__ trans,
                      float* __restrict__ out) {
    int b = blockIdx.x;
    int j = threadIdx.x;
    int jj = (j < NTAG) ? j : 0;

    __shared__ unsigned char bp[TT][NTAG];
    __shared__ int tags[TT];

    float tr[NTAG];
#pragma unroll
    for (int i = 0; i < NTAG; i++) tr[i] = trans[i * NTAG + jj];

    float alpha = __fadd_rn(trans[BOST * NTAG + jj], g_emis[b][0][jj]);

    for (int t = 1; t < TT; t++) {
        float e = g_emis[b][t][jj];
        bool m = (x[b * TT + t] != PADT);
        float best = -1e30f;
        int bi = 0;
#pragma unroll
        for (int i = 0; i < NTAG; i++) {
            float ai = __shfl_sync(0xffffffffu, alpha, i);
            float sc = __fadd_rn(ai, tr[i]);
            if (sc > best) { best = sc; bi = i; }   // strict >: first max (jnp.argmax)
        }
        float na = __fadd_rn(best, e);
        int nb = m ? bi : jj;                        // identity when masked
        alpha = m ? na : alpha;
        if (j < NTAG) bp[t][j] = (unsigned char)nb;
    }

    float fin = (j < NTAG) ? __fadd_rn(alpha, trans[jj * NTAG + EOST]) : -1e30f;
    int bidx = j;
#pragma unroll
    for (int o = 16; o > 0; o >>= 1) {
        float ov = __shfl_down_sync(0xffffffffu, fin, o);
        int oi = __shfl_down_sync(0xffffffffu, bidx, o);
        if (ov > fin || (ov == fin && oi < bidx)) { fin = ov; bidx = oi; }
    }
    int tag = __shfl_sync(0xffffffffu, bidx, 0);
    float score = __shfl_sync(0xffffffffu, fin, 0);
    __syncwarp();
    if (j == 0) {
        out[b] = score;
        int tg = tag;
        tags[TT - 1] = tg;
        for (int t = TT - 1; t >= 1; t--) { tg = bp[t][tg]; tags[t - 1] = tg; }
    }
    __syncwarp();
    for (int t = j; t < TT; t += 32) {
        bool m = (x[b * TT + t] != PADT);
        out[BB + b * TT + t] = m ? (float)tags[t] : (float)PADT;
    }
}

// ---------------- launch ----------------
extern "C" void kernel_launch(void* const* d_in, const int* in_sizes, int n_in,
                              void* d_out, int out_size) {
    const int*   x     = (const int*)d_in[0];
    const float* emb   = (const float*)d_in[1];
    const float* wihf  = (const float*)d_in[2];
    const float* whhf  = (const float*)d_in[3];
    const float* bf    = (const float*)d_in[4];
    const float* wihb  = (const float*)d_in[5];
    const float* whhb  = (const float*)d_in[6];
    const float* bb    = (const float*)d_in[7];
    const float* fcw   = (const float*)d_in[8];
    const float* fcb   = (const float*)d_in[9];
    const float* fc2w  = (const float*)d_in[10];
    const float* fc2b  = (const float*)d_in[11];
    const float* trans = (const float*)d_in[12];
    float* out = (float*)d_out;

    k_init<<<256, 256>>>();
    k_proj<<<dim3(BB * TT / 128, GG / 128, 2), 256>>>(x, emb, wihf, wihb);
    for (int s = 0; s < TT; s++)
        k_step<<<dim3(HH / 8, 2), 128>>>(x, whhf, whhb, bf, bb, s);
    k_emis<<<BB * TT / 8, 256>>>(fcw, fcb);
    k_cls<<<BB, 32>>>(fc2w, fc2b, out);
    k_vit<<<BB, 32>>>(x, trans, out);
}

// round 7
// speedup vs baseline: 1.2745x; 1.2745x over previous
#include <cuda_runtime.h>
#include <math.h>

#define BB   64
#define TT   512
#define EE   256
#define HH   512
#define GG   2048   // 4*H
#define NTAG 12
#define NCLS 10
#define PADT 0
#define BOST 10
#define EOST 11

typedef unsigned long long ull;

// ---------------- scratch (device globals; allocation-free) ----------------
__device__ __align__(16) float g_xproj[(size_t)2 * TT * 64 * GG];   // [dir][t][blk][b][32]
__device__ __align__(16) float g_hdup[2 * 2 * HH * 128];            // [phase][dir][k][2b dup]
__device__ __align__(16) float g_hout[(size_t)2 * BB * TT * HH];    // [dir][b][t][hh], masked (R2 layout)
__device__ __align__(16) float g_emis[BB][TT][NTAG];
__device__ unsigned g_cnt[2];
__device__ unsigned g_gen[2];

// ---------------- low-level helpers ----------------
__device__ __forceinline__ ull ffma2(ull a, ull b, ull c) {
    ull d;
    asm("fma.rn.f32x2 %0, %1, %2, %3;" : "=l"(d) : "l"(a), "l"(b), "l"(c));
    return d;
}
__device__ __forceinline__ ull fdup(float x) {
    ull r;
    asm("mov.b64 %0, {%1, %1};" : "=l"(r) : "f"(x));
    return r;
}
__device__ __forceinline__ float f2lo(ull v) { return __uint_as_float((unsigned)v); }
__device__ __forceinline__ float f2hi(ull v) { return __uint_as_float((unsigned)(v >> 32)); }

__device__ __forceinline__ unsigned s2u(const void* p) {
    unsigned r;
    asm("{.reg .u64 t; cvta.to.shared.u64 t, %1; cvt.u32.u64 %0, t;}" : "=r"(r) : "l"(p));
    return r;
}
__device__ __forceinline__ void cp16(unsigned dst, const void* src) {
    asm volatile("cp.async.cg.shared.global [%0], [%1], 16;" :: "r"(dst), "l"(src));
}
#define CP_COMMIT() asm volatile("cp.async.commit_group;" ::: "memory")
#define CP_WAIT(N)  asm volatile("cp.async.wait_group " #N ";" ::: "memory")

// ---------------- XLA-matching elementwise math ----------------
__device__ __forceinline__ float xla_tanh(float x) {
    if (fabsf(x) < 0.0004f) return x;
    float xc = fminf(fmaxf(x, -7.90531110689510f), 7.90531110689510f);
    float x2 = __fmul_rn(xc, xc);
    float p = -2.76076847742355e-16f;
    p = fmaf(p, x2, 2.00018790482477e-13f);
    p = fmaf(p, x2, -8.60467152213735e-11f);
    p = fmaf(p, x2, 5.12229709037114e-08f);
    p = fmaf(p, x2, 1.48572235717979e-05f);
    p = fmaf(p, x2, 6.37261928875436e-04f);
    p = fmaf(p, x2, 4.89352455891786e-03f);
    p = __fmul_rn(xc, p);
    float q = 1.19825839466702e-06f;
    q = fmaf(q, x2, 1.18534705686654e-04f);
    q = fmaf(q, x2, 2.26843463243900e-03f);
    q = fmaf(q, x2, 4.89352518554385e-03f);
    return __fdiv_rn(p, q);
}
__device__ __forceinline__ float xla_sigmoid(float x) {
    return __fdiv_rn(1.0f, __fadd_rn(1.0f, expf(-x)));
}

// ---------------- init: zero h(dup, both phases) + barrier counters ----------------
__global__ void k_init() {
    int i = blockIdx.x * blockDim.x + threadIdx.x;
    if (i < 2 * 2 * HH * 128) g_hdup[i] = 0.0f;
    if (i < 2) { g_cnt[i] = 0; g_gen[i] = 0; }
}

// ---------------- input projection GEMM (f32x2, no bias) ----------------
// out[(dir,t,blk)][b][32]: 32 cols = q*8+hl for hh in [blk*8, blk*8+8)
__global__ __launch_bounds__(256) void k_proj(const int* __restrict__ x,
                                              const float* __restrict__ emb,
                                              const float* __restrict__ wf,
                                              const float* __restrict__ wb) {
    const int dir = blockIdx.z;
    const float* __restrict__ W = dir ? wb : wf;
    const int m0 = blockIdx.x * 128;
    const int n0 = blockIdx.y * 128;

    __shared__ int toks[128];
    __shared__ __align__(16) float As[16 * 132];
    __shared__ __align__(16) float Bs[16 * 132];

    const int tid = threadIdx.x;
    if (tid < 128) toks[tid] = x[m0 + tid];
    __syncthreads();

    const int ty = tid >> 4;
    const int tx = tid & 15;

    const float* arow[8];
    const float* brow[8];
#pragma unroll
    for (int i = 0; i < 8; i++) {
        int lin = i * 256 + tid;
        int mi  = lin >> 4;
        arow[i] = emb + (size_t)toks[mi] * EE;
        brow[i] = W + (size_t)(n0 + mi) * EE;
    }

    ull acc[8][4];
#pragma unroll
    for (int i = 0; i < 8; i++)
#pragma unroll
        for (int j = 0; j < 4; j++) acc[i][j] = 0ull;

    for (int k0 = 0; k0 < EE; k0 += 16) {
#pragma unroll
        for (int i = 0; i < 8; i++) {
            int lin = i * 256 + tid;
            int ki = lin & 15, mi = lin >> 4;
            As[ki * 132 + mi] = arow[i][k0 + ki];
            Bs[ki * 132 + mi] = brow[i][k0 + ki];
        }
        __syncthreads();
#pragma unroll
        for (int k = 0; k < 16; k++) {
            float4 a0 = *(const float4*)&As[k * 132 + ty * 8];
            float4 a1 = *(const float4*)&As[k * 132 + ty * 8 + 4];
            ull b01 = *(const ull*)&Bs[k * 132 + tx * 8];
            ull b23 = *(const ull*)&Bs[k * 132 + tx * 8 + 2];
            ull b45 = *(const ull*)&Bs[k * 132 + tx * 8 + 4];
            ull b67 = *(const ull*)&Bs[k * 132 + tx * 8 + 6];
            float av[8] = {a0.x, a0.y, a0.z, a0.w, a1.x, a1.y, a1.z, a1.w};
#pragma unroll
            for (int i = 0; i < 8; i++) {
                ull ad = fdup(av[i]);
                acc[i][0] = ffma2(ad, b01, acc[i][0]);
                acc[i][1] = ffma2(ad, b23, acc[i][1]);
                acc[i][2] = ffma2(ad, b45, acc[i][2]);
                acc[i][3] = ffma2(ad, b67, acc[i][3]);
            }
        }
        __syncthreads();
    }

    const int n = n0 + tx * 8;       // 8 consecutive cols: same q, same blk, hl 0..7
    const int q   = n >> 9;
    const int hhb = n & 511;
    const int blk = hhb >> 3;
#pragma unroll
    for (int i = 0; i < 8; i++) {
        int m = m0 + ty * 8 + i;
        int b = m >> 9;
        int t = m & (TT - 1);
        size_t base = (((size_t)(dir * TT + t) * 64 + blk) * 64 + b) * 32 + q * 8;
        float4 v0 = make_float4(f2lo(acc[i][0]), f2hi(acc[i][0]),
                                f2lo(acc[i][1]), f2hi(acc[i][1]));
        float4 v1 = make_float4(f2lo(acc[i][2]), f2hi(acc[i][2]),
                                f2lo(acc[i][3]), f2hi(acc[i][3]));
        *(float4*)&g_xproj[base]     = v0;
        *(float4*)&g_xproj[base + 4] = v1;
    }
}

// ---------------- persistent BiLSTM recurrence ----------------
// 128 CTAs x 128 threads. CTA (dir, blk) owns 8 h-indices (32 gate cols).
__global__ __launch_bounds__(128, 1) void k_rec(const int* __restrict__ x,
                                                const float* __restrict__ whf,
                                                const float* __restrict__ whb,
                                                const float* __restrict__ bfp,
                                                const float* __restrict__ bbp) {
    extern __shared__ __align__(16) float sm[];
    float* Ws   = sm;            // 16384 floats  [k][32]
    float* Hs   = sm + 16384;    // 16384 floats  2 bufs x [k(64)][128 dup]
    float* Cs   = sm + 32768;    // 512 floats    [hl][b]
    float* Bias = sm + 33280;    // 32 floats

    const int tid = threadIdx.x;
    const int dir = blockIdx.x >> 6;
    const int blk = blockIdx.x & 63;
    const int hh0 = blk * 8;
    const int ty  = tid >> 2;    // 0..31 -> b pair (2ty, 2ty+1)
    const int tx  = tid & 3;     // 0..3  -> hl pair (2tx, 2tx+1)
    const float* __restrict__ W    = dir ? whb : whf;
    const float* __restrict__ bias = dir ? bbp : bfp;

    // load W slice (transposed to k-major) once
    for (int idx = tid; idx < 32 * 512; idx += 128) {
        int c = idx >> 9, k = idx & 511;
        Ws[k * 32 + c] = W[(size_t)((c >> 3) * HH + hh0 + (c & 7)) * HH + k];
    }
    if (tid < 32) Bias[tid] = bias[(tid >> 3) * HH + hh0 + (tid & 7)];
    for (int i = tid; i < 512; i += 128) Cs[i] = 0.0f;
    __syncthreads();

    const unsigned hs_u = s2u(Hs);
    int p = 0;

    for (int s = 0; s < TT; s++) {
        const int t = dir ? (TT - 1 - s) : s;
        const float* hsrc = g_hdup + (size_t)(p * 2 + dir) * HH * 128;

        // stage chunk 0 -> buf 0
        for (int i = tid; i < 2048; i += 128)
            cp16(hs_u + i * 16, (const char*)hsrc + i * 16);
        CP_COMMIT();

        ull a00 = 0, a01 = 0, a02 = 0, a03 = 0;
        ull a10 = 0, a11 = 0, a12 = 0, a13 = 0;
        int buf = 0;

        for (int ch = 0; ch < 8; ch++) {
            if (ch < 7) {
                const char* src = (const char*)(hsrc + (size_t)(ch + 1) * 64 * 128);
                unsigned d = hs_u + (unsigned)((buf ^ 1) * 32768);
                for (int i = tid; i < 2048; i += 128)
                    cp16(d + i * 16, src + i * 16);
                CP_COMMIT();
                CP_WAIT(1);
            } else {
                CP_WAIT(0);
            }
            __syncthreads();

            const float* Hb = Hs + buf * 8192;
            const float* Wb = Ws + ch * 2048;
#pragma unroll 4
            for (int kk = 0; kk < 64; kk++) {
                const float* hr = Hb + kk * 128 + 4 * ty;
                ull ha = *(const ull*)hr;
                ull hb2 = *(const ull*)(hr + 2);
                const float* wr = Wb + kk * 32 + 2 * tx;
                ull w0 = *(const ull*)(wr);
                ull w1 = *(const ull*)(wr + 8);
                ull w2 = *(const ull*)(wr + 16);
                ull w3 = *(const ull*)(wr + 24);
                a00 = ffma2(ha, w0, a00);  a01 = ffma2(ha, w1, a01);
                a02 = ffma2(ha, w2, a02);  a03 = ffma2(ha, w3, a03);
                a10 = ffma2(hb2, w0, a10); a11 = ffma2(hb2, w1, a11);
                a12 = ffma2(hb2, w2, a12); a13 = ffma2(hb2, w3, a13);
            }
            buf ^= 1;
            __syncthreads();
        }

        // ---- fused LSTM cell
        {
            const int pn = p ^ 1;
            const size_t xbase = ((size_t)(dir * TT + t) * 64 + blk) * 2048;
            float* hdst = g_hdup + (size_t)(pn * 2 + dir) * HH * 128;
            const float* hold = g_hdup + (size_t)(p * 2 + dir) * HH * 128;

#pragma unroll
            for (int bi = 0; bi < 2; bi++) {
                const int b = 2 * ty + bi;
                const bool m = (x[b * TT + t] != PADT);
                const float* xp = g_xproj + xbase + b * 32;
                float* houtt = g_hout + (((size_t)dir * BB + b) * TT + t) * HH;
                ull ac0 = bi ? a10 : a00;
                ull ac1 = bi ? a11 : a01;
                ull ac2 = bi ? a12 : a02;
                ull ac3 = bi ? a13 : a03;
                float gl[4], gh[4];
                {
                    int c = 0 * 8 + 2 * tx;
                    float2 xv = *(const float2*)(xp + c);
                    gl[0] = __fadd_rn(__fadd_rn(xv.x, f2lo(ac0)), Bias[c]);
                    gh[0] = __fadd_rn(__fadd_rn(xv.y, f2hi(ac0)), Bias[c + 1]);
                }
                {
                    int c = 1 * 8 + 2 * tx;
                    float2 xv = *(const float2*)(xp + c);
                    gl[1] = __fadd_rn(__fadd_rn(xv.x, f2lo(ac1)), Bias[c]);
                    gh[1] = __fadd_rn(__fadd_rn(xv.y, f2hi(ac1)), Bias[c + 1]);
                }
                {
                    int c = 2 * 8 + 2 * tx;
                    float2 xv = *(const float2*)(xp + c);
                    gl[2] = __fadd_rn(__fadd_rn(xv.x, f2lo(ac2)), Bias[c]);
                    gh[2] = __fadd_rn(__fadd_rn(xv.y, f2hi(ac2)), Bias[c + 1]);
                }
                {
                    int c = 3 * 8 + 2 * tx;
                    float2 xv = *(const float2*)(xp + c);
                    gl[3] = __fadd_rn(__fadd_rn(xv.x, f2lo(ac3)), Bias[c]);
                    gh[3] = __fadd_rn(__fadd_rn(xv.y, f2hi(ac3)), Bias[c + 1]);
                }
#pragma unroll
                for (int li = 0; li < 2; li++) {
                    float iv = li ? gh[0] : gl[0];
                    float fv = li ? gh[1] : gl[1];
                    float gv = li ? gh[2] : gl[2];
                    float ov = li ? gh[3] : gl[3];
                    int hl = 2 * tx + li, hh = hh0 + hl;
                    float co = Cs[hl * 64 + b];
                    float ho = hold[hh * 128 + 2 * b];
                    float si = xla_sigmoid(iv);
                    float sf = xla_sigmoid(fv);
                    float so = xla_sigmoid(ov);
                    float tg = xla_tanh(gv);
                    float cn = __fadd_rn(__fmul_rn(sf, co), __fmul_rn(si, tg));
                    float hc = __fmul_rn(so, xla_tanh(cn));
                    Cs[hl * 64 + b] = m ? cn : co;
                    float hn = m ? hc : ho;
                    *(ull*)(hdst + hh * 128 + 2 * b) = fdup(hn);
                    houtt[hh] = m ? hc : 0.0f;
                }
            }
        }

        // ---- grid barrier (per direction, 64 CTAs)
        __syncthreads();
        if (tid == 0) {
            __threadfence();
            unsigned target = (unsigned)(s + 1);
            unsigned old = atomicAdd(&g_cnt[dir], 1);
            if (old == 63) {
                atomicExch(&g_cnt[dir], 0);
                __threadfence();
                atomicExch(&g_gen[dir], target);
            } else {
                while (*(volatile unsigned*)&g_gen[dir] < target) __nanosleep(64);
            }
            __threadfence();
        }
        __syncthreads();
        p ^= 1;
    }
}

// ---------------- emissions: warp per (b,t) — EXACT round-2 reduction order ----------------
__global__ __launch_bounds__(256) void k_emis(const float* __restrict__ fcw,
                                              const float* __restrict__ fcb) {
    int w = blockIdx.x * 8 + (threadIdx.x >> 5);
    int lane = threadIdx.x & 31;
    int b = w >> 9;
    int t = w & (TT - 1);
    const float* __restrict__ hf = g_hout + (((size_t)0 * BB + b) * TT + t) * HH;
    const float* __restrict__ hb = g_hout + (((size_t)1 * BB + b) * TT + t) * HH;
    float acc[NTAG];
#pragma unroll
    for (int j = 0; j < NTAG; j++) acc[j] = 0.0f;
    for (int it = 0; it < 32; it++) {
        int k = it * 32 + lane;
        float hv = (k < HH) ? hf[k] : hb[k - HH];
#pragma unroll
        for (int j = 0; j < NTAG; j++) acc[j] = fmaf(hv, fcw[j * (2 * HH) + k], acc[j]);
    }
#pragma unroll
    for (int j = 0; j < NTAG; j++)
#pragma unroll
        for (int o = 16; o > 0; o >>= 1) acc[j] += __shfl_xor_sync(0xffffffffu, acc[j], o);
    if (lane == 0) {
#pragma unroll
        for (int j = 0; j < NTAG; j++) g_emis[b][t][j] = __fadd_rn(acc[j], fcb[j]);
    }
}

// ---------------- class probabilities: warp per batch ----------------
__global__ void k_cls(const float* __restrict__ fc2w, const float* __restrict__ fc2b,
                      float* __restrict__ out) {
    int b = blockIdx.x;
    int lane = threadIdx.x;
    // final phase = 0 after 512 flips
    const float* __restrict__ hf = g_hdup;                       // dir 0
    const float* __restrict__ hb = g_hdup + (size_t)HH * 128;    // dir 1
    float logit[NCLS];
#pragma unroll
    for (int j = 0; j < NCLS; j++) {
        float p = 0.0f;
        for (int it = 0; it < 32; it++) {
            int k = it * 32 + lane;
            float hv = (k < HH) ? hf[k * 128 + 2 * b] : hb[(k - HH) * 128 + 2 * b];
            p = fmaf(hv, fc2w[j * (2 * HH) + k], p);
        }
#pragma unroll
        for (int o = 16; o > 0; o >>= 1) p += __shfl_xor_sync(0xffffffffu, p, o);
        logit[j] = __fadd_rn(p, fc2b[j]);
    }
    float mx = logit[0];
#pragma unroll
    for (int j = 1; j < NCLS; j++) mx = fmaxf(mx, logit[j]);
    float ex[NCLS];
    float sum = 0.0f;
#pragma unroll
    for (int j = 0; j < NCLS; j++) {
        ex[j] = expf(__fadd_rn(logit[j], -mx));
        sum = __fadd_rn(sum, ex[j]);
    }
    if (lane == 0) {
        float* o = out + BB + BB * TT + b * NCLS;
#pragma unroll
        for (int j = 0; j < NCLS; j++) o[j] = __fdiv_rn(ex[j], sum);
    }
}

// ---------------- Viterbi: warp per batch, backpointers in SMEM ----------------
__global__ void k_vit(const int* __restrict__ x, const float* __restrict__ trans,
                      float* __restrict__ out) {
    int b = blockIdx.x;
    int j = threadIdx.x;
    int jj = (j < NTAG) ? j : 0;

    __shared__ unsigned char bp[TT][NTAG];
    __shared__ int tags[TT];

    float tr[NTAG];
#pragma unroll
    for (int i = 0; i < NTAG; i++) tr[i] = trans[i * NTAG + jj];

    float alpha = __fadd_rn(trans[BOST * NTAG + jj], g_emis[b][0][jj]);

    for (int t = 1; t < TT; t++) {
        float e = g_emis[b][t][jj];
        bool m = (x[b * TT + t] != PADT);
        float best = -1e30f;
        int bi = 0;
#pragma unroll
        for (int i = 0; i < NTAG; i++) {
            float ai = __shfl_sync(0xffffffffu, alpha, i);
            float sc = __fadd_rn(ai, tr[i]);
            if (sc > best) { best = sc; bi = i; }   // strict >: first max (jnp.argmax)
        }
        float na = __fadd_rn(best, e);
        int nb = m ? bi : jj;
        alpha = m ? na : alpha;
        if (j < NTAG) bp[t][j] = (unsigned char)nb;
    }

    float fin = (j < NTAG) ? __fadd_rn(alpha, trans[jj * NTAG + EOST]) : -1e30f;
    int bidx = j;
#pragma unroll
    for (int o = 16; o > 0; o >>= 1) {
        float ov = __shfl_down_sync(0xffffffffu, fin, o);
        int oi = __shfl_down_sync(0xffffffffu, bidx, o);
        if (ov > fin || (ov == fin && oi < bidx)) { fin = ov; bidx = oi; }
    }
    int tag = __shfl_sync(0xffffffffu, bidx, 0);
    float score = __shfl_sync(0xffffffffu, fin, 0);
    __syncwarp();
    if (j == 0) {
        out[b] = score;
        int tg = tag;
        tags[TT - 1] = tg;
        for (int t = TT - 1; t >= 1; t--) { tg = bp[t][tg]; tags[t - 1] = tg; }
    }
    __syncwarp();
    for (int t = j; t < TT; t += 32) {
        bool m = (x[b * TT + t] != PADT);
        out[BB + b * TT + t] = m ? (float)tags[t] : (float)PADT;
    }
}

// ---------------- launch ----------------
extern "C" void kernel_launch(void* const* d_in, const int* in_sizes, int n_in,
                              void* d_out, int out_size) {
    const int*   x     = (const int*)d_in[0];
    const float* emb   = (const float*)d_in[1];
    const float* wihf  = (const float*)d_in[2];
    const float* whhf  = (const float*)d_in[3];
    const float* bf    = (const float*)d_in[4];
    const float* wihb  = (const float*)d_in[5];
    const float* whhb  = (const float*)d_in[6];
    const float* bb    = (const float*)d_in[7];
    const float* fcw   = (const float*)d_in[8];
    const float* fcb   = (const float*)d_in[9];
    const float* fc2w  = (const float*)d_in[10];
    const float* fc2b  = (const float*)d_in[11];
    const float* trans = (const float*)d_in[12];
    float* out = (float*)d_out;

    cudaFuncSetAttribute(k_rec, cudaFuncAttributeMaxDynamicSharedMemorySize, 133248);

    k_init<<<1024, 256>>>();
    k_proj<<<dim3(BB * TT / 128, GG / 128, 2), 256>>>(x, emb, wihf, wihb);
    k_rec<<<128, 128, 133248>>>(x, whhf, whhb, bf, bb);
    k_emis<<<BB * TT / 8, 256>>>(fcw, fcb);
    k_cls<<<BB, 32>>>(fc2w, fc2b, out);
    k_vit<<<BB, 32>>>(x, trans, out);
}

// round 9
// speedup vs baseline: 1.6854x; 1.3224x over previous
#include <cuda_runtime.h>
#include <math.h>

#define BB   64
#define TT   512
#define EE   256
#define HH   512
#define GG   2048   // 4*H
#define NTAG 12
#define NCLS 10
#define PADT 0
#define BOST 10
#define EOST 11

typedef unsigned long long ull;

// ---------------- scratch (device globals; allocation-free) ----------------
__device__ __align__(16) float g_xproj[(size_t)2 * TT * 64 * GG];   // [dir][t][blk][b][32]
__device__ __align__(16) float g_h[2 * 2 * HH * BB];                // [phase][dir][k][b]  (non-dup)
__device__ __align__(16) float g_hout[(size_t)2 * BB * TT * HH];    // [dir][b][t][hh], masked
__device__ __align__(16) float g_emis[BB][TT][NTAG];
__device__ unsigned g_cnt[2];

// ---------------- low-level helpers ----------------
__device__ __forceinline__ ull ffma2(ull a, ull b, ull c) {
    ull d;
    asm("fma.rn.f32x2 %0, %1, %2, %3;" : "=l"(d) : "l"(a), "l"(b), "l"(c));
    return d;
}
__device__ __forceinline__ ull fdup(float x) {
    ull r;
    asm("mov.b64 %0, {%1, %1};" : "=l"(r) : "f"(x));
    return r;
}
__device__ __forceinline__ float f2lo(ull v) { return __uint_as_float((unsigned)v); }
__device__ __forceinline__ float f2hi(ull v) { return __uint_as_float((unsigned)(v >> 32)); }

__device__ __forceinline__ unsigned s2u(const void* p) {
    unsigned r;
    asm("{.reg .u64 t; cvta.to.shared.u64 t, %1; cvt.u32.u64 %0, t;}" : "=r"(r) : "l"(p));
    return r;
}
__device__ __forceinline__ void cp16(unsigned dst, const void* src) {
    asm volatile("cp.async.cg.shared.global [%0], [%1], 16;" :: "r"(dst), "l"(src));
}
#define CP_COMMIT() asm volatile("cp.async.commit_group;" ::: "memory")
#define CP_WAIT(N)  asm volatile("cp.async.wait_group " #N ";" ::: "memory")

// ---------------- XLA-matching elementwise math ----------------
__device__ __forceinline__ float xla_tanh(float x) {
    if (fabsf(x) < 0.0004f) return x;
    float xc = fminf(fmaxf(x, -7.90531110689510f), 7.90531110689510f);
    float x2 = __fmul_rn(xc, xc);
    float p = -2.76076847742355e-16f;
    p = fmaf(p, x2, 2.00018790482477e-13f);
    p = fmaf(p, x2, -8.60467152213735e-11f);
    p = fmaf(p, x2, 5.12229709037114e-08f);
    p = fmaf(p, x2, 1.48572235717979e-05f);
    p = fmaf(p, x2, 6.37261928875436e-04f);
    p = fmaf(p, x2, 4.89352455891786e-03f);
    p = __fmul_rn(xc, p);
    float q = 1.19825839466702e-06f;
    q = fmaf(q, x2, 1.18534705686654e-04f);
    q = fmaf(q, x2, 2.26843463243900e-03f);
    q = fmaf(q, x2, 4.89352518554385e-03f);
    return __fdiv_rn(p, q);
}
__device__ __forceinline__ float xla_sigmoid(float x) {
    return __fdiv_rn(1.0f, __fadd_rn(1.0f, expf(-x)));
}

// ---------------- init ----------------
__global__ void k_init() {
    int i = blockIdx.x * blockDim.x + threadIdx.x;
    if (i < 2 * 2 * HH * BB) g_h[i] = 0.0f;
    if (i < 2) g_cnt[i] = 0;
}

// ---------------- input projection GEMM (f32x2, no bias) — unchanged ----------------
__global__ __launch_bounds__(256) void k_proj(const int* __restrict__ x,
                                              const float* __restrict__ emb,
                                              const float* __restrict__ wf,
                                              const float* __restrict__ wb) {
    const int dir = blockIdx.z;
    const float* __restrict__ W = dir ? wb : wf;
    const int m0 = blockIdx.x * 128;
    const int n0 = blockIdx.y * 128;

    __shared__ int toks[128];
    __shared__ __align__(16) float As[16 * 132];
    __shared__ __align__(16) float Bs[16 * 132];

    const int tid = threadIdx.x;
    if (tid < 128) toks[tid] = x[m0 + tid];
    __syncthreads();

    const int ty = tid >> 4;
    const int tx = tid & 15;

    const float* arow[8];
    const float* brow[8];
#pragma unroll
    for (int i = 0; i < 8; i++) {
        int lin = i * 256 + tid;
        int mi  = lin >> 4;
        arow[i] = emb + (size_t)toks[mi] * EE;
        brow[i] = W + (size_t)(n0 + mi) * EE;
    }

    ull acc[8][4];
#pragma unroll
    for (int i = 0; i < 8; i++)
#pragma unroll
        for (int j = 0; j < 4; j++) acc[i][j] = 0ull;

    for (int k0 = 0; k0 < EE; k0 += 16) {
#pragma unroll
        for (int i = 0; i < 8; i++) {
            int lin = i * 256 + tid;
            int ki = lin & 15, mi = lin >> 4;
            As[ki * 132 + mi] = arow[i][k0 + ki];
            Bs[ki * 132 + mi] = brow[i][k0 + ki];
        }
        __syncthreads();
#pragma unroll
        for (int k = 0; k < 16; k++) {
            float4 a0 = *(const float4*)&As[k * 132 + ty * 8];
            float4 a1 = *(const float4*)&As[k * 132 + ty * 8 + 4];
            ull b01 = *(const ull*)&Bs[k * 132 + tx * 8];
            ull b23 = *(const ull*)&Bs[k * 132 + tx * 8 + 2];
            ull b45 = *(const ull*)&Bs[k * 132 + tx * 8 + 4];
            ull b67 = *(const ull*)&Bs[k * 132 + tx * 8 + 6];
            float av[8] = {a0.x, a0.y, a0.z, a0.w, a1.x, a1.y, a1.z, a1.w};
#pragma unroll
            for (int i = 0; i < 8; i++) {
                ull ad = fdup(av[i]);
                acc[i][0] = ffma2(ad, b01, acc[i][0]);
                acc[i][1] = ffma2(ad, b23, acc[i][1]);
                acc[i][2] = ffma2(ad, b45, acc[i][2]);
                acc[i][3] = ffma2(ad, b67, acc[i][3]);
            }
        }
        __syncthreads();
    }

    const int n = n0 + tx * 8;
    const int q   = n >> 9;
    const int hhb = n & 511;
    const int blk = hhb >> 3;
#pragma unroll
    for (int i = 0; i < 8; i++) {
        int m = m0 + ty * 8 + i;
        int b = m >> 9;
        int t = m & (TT - 1);
        size_t base = (((size_t)(dir * TT + t) * 64 + blk) * 64 + b) * 32 + q * 8;
        float4 v0 = make_float4(f2lo(acc[i][0]), f2hi(acc[i][0]),
                                f2lo(acc[i][1]), f2hi(acc[i][1]));
        float4 v1 = make_float4(f2lo(acc[i][2]), f2hi(acc[i][2]),
                                f2lo(acc[i][3]), f2hi(acc[i][3]));
        *(float4*)&g_xproj[base]     = v0;
        *(float4*)&g_xproj[base + 4] = v1;
    }
}

// ---------------- persistent BiLSTM recurrence (broadcast-LDS layout) ----------------
// 128 CTAs x 128 threads. CTA (dir, blk) owns 8 h-indices (32 gate cols).
// Warp w owns gate cols {q*8 + 2w, q*8 + 2w + 1 : q=0..3}; lane l owns b-pair (2l, 2l+1).
// W loads are warp-uniform LDS broadcasts (~free BW); h loads 1 LDS.64/lane.
// Cell state c in registers; bias in registers; no gate smem round-trip.
__global__ __launch_bounds__(128, 1) void k_rec(const int* __restrict__ x,
                                                const float* __restrict__ whf,
                                                const float* __restrict__ whb,
                                                const float* __restrict__ bfp,
                                                const float* __restrict__ bbp) {
    extern __shared__ __align__(16) float sm[];
    float* Ws = sm;                 // 512 * 34 floats (stride 34 keeps 8B align, kills STS conflicts)
    float* Hs = sm + 512 * 34;      // 2 bufs x 64k x 64b floats

    const int tid = threadIdx.x;
    const int dir = blockIdx.x >> 6;
    const int blk = blockIdx.x & 63;
    const int hh0 = blk * 8;
    const int w   = tid >> 5;       // warp 0..3
    const int l   = tid & 31;
    const int b0  = 2 * l;
    const int hl0 = 2 * w;

    const float* __restrict__ W    = dir ? whb : whf;
    const float* __restrict__ bias = dir ? bbp : bfp;

    // load W slice once: Ws[k*34 + c], c = q*8+hl, from W[(q*HH + hh0+hl)*HH + k]
    for (int idx = tid; idx < 32 * 512; idx += 128) {
        int k = idx & 511, c = idx >> 9;
        Ws[k * 34 + c] = W[(size_t)((c >> 3) * HH + hh0 + (c & 7)) * HH + k];
    }
    float2 bs[4];
#pragma unroll
    for (int q = 0; q < 4; q++)
        bs[q] = *(const float2*)&bias[q * HH + hh0 + hl0];

    float creg[2][2] = {{0.0f, 0.0f}, {0.0f, 0.0f}};   // [bi][li]
    __syncthreads();

    const unsigned hs_u = s2u(Hs);
    int p = 0;

    for (int s = 0; s < TT; s++) {
        const int t = dir ? (TT - 1 - s) : s;
        const float* hsrc = g_h + (size_t)(p * 2 + dir) * HH * BB;

        // early independent loads (xproj, mask, h_old) — latency hidden under staging/compute
        const size_t xbase = ((size_t)(dir * TT + t) * 64 + blk) * 2048;
        float2 xp0[4], xp1[4];
#pragma unroll
        for (int q = 0; q < 4; q++) {
            xp0[q] = *(const float2*)&g_xproj[xbase + (size_t)b0 * 32 + q * 8 + hl0];
            xp1[q] = *(const float2*)&g_xproj[xbase + (size_t)(b0 + 1) * 32 + q * 8 + hl0];
        }
        const bool m0 = (x[b0 * TT + t] != PADT);
        const bool m1 = (x[(b0 + 1) * TT + t] != PADT);
        const float2 hold0 = *(const float2*)&hsrc[(hh0 + hl0)     * BB + b0]; // (h_prev[hl0][b0], [b1])
        const float2 hold1 = *(const float2*)&hsrc[(hh0 + hl0 + 1) * BB + b0];

        // stage chunk 0 (16 KB)
        for (int i = tid; i < 1024; i += 128)
            cp16(hs_u + i * 16, (const char*)hsrc + i * 16);
        CP_COMMIT();

        ull a00 = 0, a01 = 0, a02 = 0, a03 = 0;
        ull a10 = 0, a11 = 0, a12 = 0, a13 = 0;
        int buf = 0;

        for (int ch = 0; ch < 8; ch++) {
            if (ch < 7) {
                const char* src = (const char*)(hsrc + (size_t)(ch + 1) * 64 * BB);
                unsigned d = hs_u + (unsigned)((buf ^ 1) * 16384);
                for (int i = tid; i < 1024; i += 128)
                    cp16(d + i * 16, src + i * 16);
                CP_COMMIT();
                CP_WAIT(1);
            } else {
                CP_WAIT(0);
            }
            __syncthreads();

            const float* Hb = Hs + buf * 4096;
            const float* Wc = Ws + (ch * 64) * 34 + hl0;
#pragma unroll 8
            for (int kk = 0; kk < 64; kk++) {
                ull hp = *(const ull*)(Hb + kk * 64 + b0);     // (h[b0], h[b1])
                ull h0 = fdup(f2lo(hp));
                ull h1 = fdup(f2hi(hp));
                const float* wr = Wc + kk * 34;                // warp-uniform -> broadcast
                ull w0 = *(const ull*)(wr);
                ull w1 = *(const ull*)(wr + 8);
                ull w2 = *(const ull*)(wr + 16);
                ull w3 = *(const ull*)(wr + 24);
                a00 = ffma2(h0, w0, a00);  a01 = ffma2(h0, w1, a01);
                a02 = ffma2(h0, w2, a02);  a03 = ffma2(h0, w3, a03);
                a10 = ffma2(h1, w0, a10);  a11 = ffma2(h1, w1, a11);
                a12 = ffma2(h1, w2, a12);  a13 = ffma2(h1, w3, a13);
            }
            buf ^= 1;
            __syncthreads();
        }

        // ---- fused LSTM cell: 4 cells/thread, all gates local, c in registers
        const int pn = p ^ 1;
        float* hdst = g_h + (size_t)(pn * 2 + dir) * HH * BB;
        float hnew[2][2], hov[2][2];
#pragma unroll
        for (int bi = 0; bi < 2; bi++) {
            const bool m = bi ? m1 : m0;
            const ull aq[4] = {bi ? a10 : a00, bi ? a11 : a01, bi ? a12 : a02, bi ? a13 : a03};
            const float2* xq = bi ? xp1 : xp0;
#pragma unroll
            for (int li = 0; li < 2; li++) {
                float iv = __fadd_rn(__fadd_rn(li ? xq[0].y : xq[0].x, li ? f2hi(aq[0]) : f2lo(aq[0])), li ? bs[0].y : bs[0].x);
                float fv = __fadd_rn(__fadd_rn(li ? xq[1].y : xq[1].x, li ? f2hi(aq[1]) : f2lo(aq[1])), li ? bs[1].y : bs[1].x);
                float gv = __fadd_rn(__fadd_rn(li ? xq[2].y : xq[2].x, li ? f2hi(aq[2]) : f2lo(aq[2])), li ? bs[2].y : bs[2].x);
                float ov = __fadd_rn(__fadd_rn(li ? xq[3].y : xq[3].x, li ? f2hi(aq[3]) : f2lo(aq[3])), li ? bs[3].y : bs[3].x);
                float co = creg[bi][li];
                float ho = li ? (bi ? hold1.y : hold1.x) : (bi ? hold0.y : hold0.x);
                float si = xla_sigmoid(iv);
                float sf = xla_sigmoid(fv);
                float so = xla_sigmoid(ov);
                float tg = xla_tanh(gv);
                float cn = __fadd_rn(__fmul_rn(sf, co), __fmul_rn(si, tg));
                float hc = __fmul_rn(so, xla_tanh(cn));
                creg[bi][li] = m ? cn : co;
                hnew[bi][li] = m ? hc : ho;
                hov[bi][li]  = m ? hc : 0.0f;
            }
        }
        *(float2*)&hdst[(hh0 + hl0)     * BB + b0] = make_float2(hnew[0][0], hnew[1][0]);
        *(float2*)&hdst[(hh0 + hl0 + 1) * BB + b0] = make_float2(hnew[0][1], hnew[1][1]);
        *(float2*)&g_hout[(((size_t)dir * BB + b0)     * TT + t) * HH + hh0 + hl0] = make_float2(hov[0][0], hov[0][1]);
        *(float2*)&g_hout[(((size_t)dir * BB + b0 + 1) * TT + t) * HH + hh0 + hl0] = make_float2(hov[1][0], hov[1][1]);

        // ---- grid barrier (per direction, 64 CTAs, monotonic counter)
        __syncthreads();
        if (tid == 0) {
            __threadfence();
            atomicAdd(&g_cnt[dir], 1u);
            const unsigned target = 64u * (unsigned)(s + 1);
            while (*(volatile unsigned*)&g_cnt[dir] < target) __nanosleep(32);
            __threadfence();
        }
        __syncthreads();
        p ^= 1;
    }
}

// ---------------- emissions: warp per (b,t) — EXACT round-2 reduction order ----------------
__global__ __launch_bounds__(256) void k_emis(const float* __restrict__ fcw,
                                              const float* __restrict__ fcb) {
    int w = blockIdx.x * 8 + (threadIdx.x >> 5);
    int lane = threadIdx.x & 31;
    int b = w >> 9;
    int t = w & (TT - 1);
    const float* __restrict__ hf = g_hout + (((size_t)0 * BB + b) * TT + t) * HH;
    const float* __restrict__ hb = g_hout + (((size_t)1 * BB + b) * TT + t) * HH;
    float acc[NTAG];
#pragma unroll
    for (int j = 0; j < NTAG; j++) acc[j] = 0.0f;
    for (int it = 0; it < 32; it++) {
        int k = it * 32 + lane;
        float hv = (k < HH) ? hf[k] : hb[k - HH];
#pragma unroll
        for (int j = 0; j < NTAG; j++) acc[j] = fmaf(hv, fcw[j * (2 * HH) + k], acc[j]);
    }
#pragma unroll
    for (int j = 0; j < NTAG; j++)
#pragma unroll
        for (int o = 16; o > 0; o >>= 1) acc[j] += __shfl_xor_sync(0xffffffffu, acc[j], o);
    if (lane == 0) {
#pragma unroll
        for (int j = 0; j < NTAG; j++) g_emis[b][t][j] = __fadd_rn(acc[j], fcb[j]);
    }
}

// ---------------- class probabilities: warp per batch ----------------
__global__ void k_cls(const float* __restrict__ fc2w, const float* __restrict__ fc2b,
                      float* __restrict__ out) {
    int b = blockIdx.x;
    int lane = threadIdx.x;
    // final h in phase 0; layout [phase][dir][k][b]: dir0 k + dir1 (k-512) collapse to k*64+b
    float logit[NCLS];
#pragma unroll
    for (int j = 0; j < NCLS; j++) {
        float p = 0.0f;
        for (int it = 0; it < 32; it++) {
            int k = it * 32 + lane;
            float hv = g_h[(size_t)k * BB + b];
            p = fmaf(hv, fc2w[j * (2 * HH) + k], p);
        }
#pragma unroll
        for (int o = 16; o > 0; o >>= 1) p += __shfl_xor_sync(0xffffffffu, p, o);
        logit[j] = __fadd_rn(p, fc2b[j]);
    }
    float mx = logit[0];
#pragma unroll
    for (int j = 1; j < NCLS; j++) mx = fmaxf(mx, logit[j]);
    float ex[NCLS];
    float sum = 0.0f;
#pragma unroll
    for (int j = 0; j < NCLS; j++) {
        ex[j] = expf(__fadd_rn(logit[j], -mx));
        sum = __fadd_rn(sum, ex[j]);
    }
    if (lane == 0) {
        float* o = out + BB + BB * TT + b * NCLS;
#pragma unroll
        for (int j = 0; j < NCLS; j++) o[j] = __fdiv_rn(ex[j], sum);
    }
}

// ---------------- Viterbi: warp per batch, backpointers in SMEM ----------------
__global__ void k_vit(const int* __restrict__ x, const float* __restrict__ trans,
                      float* __restrict__ out) {
    int b = blockIdx.x;
    int j = threadIdx.x;
    int jj = (j < NTAG) ? j : 0;

    __shared__ unsigned char bp[TT][NTAG];
    __shared__ int tags[TT];

    float tr[NTAG];
#pragma unroll
    for (int i = 0; i < NTAG; i++) tr[i] = trans[i * NTAG + jj];

    float alpha = __fadd_rn(trans[BOST * NTAG + jj], g_emis[b][0][jj]);

    for (int t = 1; t < TT; t++) {
        float e = g_emis[b][t][jj];
        bool m = (x[b * TT + t] != PADT);
        float best = -1e30f;
        int bi = 0;
#pragma unroll
        for (int i = 0; i < NTAG; i++) {
            float ai = __shfl_sync(0xffffffffu, alpha, i);
            float sc = __fadd_rn(ai, tr[i]);
            if (sc > best) { best = sc; bi = i; }   // strict >: first max (jnp.argmax)
        }
        float na = __fadd_rn(best, e);
        int nb = m ? bi : jj;
        alpha = m ? na : alpha;
        if (j < NTAG) bp[t][j] = (unsigned char)nb;
    }

    float fin = (j < NTAG) ? __fadd_rn(alpha, trans[jj * NTAG + EOST]) : -1e30f;
    int bidx = j;
#pragma unroll
    for (int o = 16; o > 0; o >>= 1) {
        float ov = __shfl_down_sync(0xffffffffu, fin, o);
        int oi = __shfl_down_sync(0xffffffffu, bidx, o);
        if (ov > fin || (ov == fin && oi < bidx)) { fin = ov; bidx = oi; }
    }
    int tag = __shfl_sync(0xffffffffu, bidx, 0);
    float score = __shfl_sync(0xffffffffu, fin, 0);
    __syncwarp();
    if (j == 0) {
        out[b] = score;
        int tg = tag;
        tags[TT - 1] = tg;
        for (int t = TT - 1; t >= 1; t--) { tg = bp[t][tg]; tags[t - 1] = tg; }
    }
    __syncwarp();
    for (int t = j; t < TT; t += 32) {
        bool m = (x[b * TT + t] != PADT);
        out[BB + b * TT + t] = m ? (float)tags[t] : (float)PADT;
    }
}

// ---------------- launch ----------------
extern "C" void kernel_launch(void* const* d_in, const int* in_sizes, int n_in,
                              void* d_out, int out_size) {
    const int*   x     = (const int*)d_in[0];
    const float* emb   = (const float*)d_in[1];
    const float* wihf  = (const float*)d_in[2];
    const float* whhf  = (const float*)d_in[3];
    const float* bf    = (const float*)d_in[4];
    const float* wihb  = (const float*)d_in[5];
    const float* whhb  = (const float*)d_in[6];
    const float* bb    = (const float*)d_in[7];
    const float* fcw   = (const float*)d_in[8];
    const float* fcb   = (const float*)d_in[9];
    const float* fc2w  = (const float*)d_in[10];
    const float* fc2b  = (const float*)d_in[11];
    const float* trans = (const float*)d_in[12];
    float* out = (float*)d_out;

    // smem: Ws 512*34*4 = 69632  +  Hs 2*64*64*4 = 32768  -> 102400
    cudaFuncSetAttribute(k_rec, cudaFuncAttributeMaxDynamicSharedMemorySize, 102400);

    k_init<<<1024, 256>>>();
    k_proj<<<dim3(BB * TT / 128, GG / 128, 2), 256>>>(x, emb, wihf, wihb);
    k_rec<<<128, 128, 102400>>>(x, whhf, whhb, bf, bb);
    k_emis<<<BB * TT / 8, 256>>>(fcw, fcb);
    k_cls<<<BB, 32>>>(fc2w, fc2b, out);
    k_vit<<<BB, 32>>>(x, trans, out);
}